// round 2
// baseline (speedup 1.0000x reference)
#include <cuda_runtime.h>
#include <cuda_bf16.h>
#include <cstdint>

// Problem constants (match reference_code)
#define N_NODES 50000
#define N_EDGES 800000
#define IN_DIM  64
#define HID_DIM 64
#define OUT_DIM 32

// Scratch: __device__ globals (allocation is forbidden)
__device__ __align__(16) float g_aggr1[N_NODES * IN_DIM];
__device__ __align__(16) float g_h[N_NODES * HID_DIM];
__device__ __align__(16) float g_aggr2[N_NODES * HID_DIM];
__device__ __align__(16) float g_cnt[N_NODES];

// ---------------------------------------------------------------------------
// Edge aggregation: for each edge e, aggr[dst] += feat[src] (64 floats),
// optionally cnt[dst] += 1. One thread handles one (edge, float4-chunk):
// 16 chunks per edge. Uses red.global.add.v4.f32 (no-return vector reduction)
// to quarter the atomic-op count.
// NOTE: edge_index is int32 on device (JAX downcasts int64 without x64 mode).
// ---------------------------------------------------------------------------
__global__ void edge_aggregate_kernel(const float* __restrict__ feat,
                                      const int* __restrict__ ei,
                                      float* __restrict__ aggr,
                                      float* __restrict__ cnt,
                                      int do_count)
{
    int idx = blockIdx.x * blockDim.x + threadIdx.x;
    const int total = N_EDGES * 16;
    if (idx >= total) return;
    int e = idx >> 4;
    int c = idx & 15;

    int src = ei[e];
    int dst = ei[N_EDGES + e];

    const float4* srow = reinterpret_cast<const float4*>(feat + (size_t)src * 64);
    float4 v = srow[c];

    float* p = aggr + (size_t)dst * 64 + c * 4;
    asm volatile("red.global.add.v4.f32 [%0], {%1, %2, %3, %4};"
                 :: "l"(p), "f"(v.x), "f"(v.y), "f"(v.z), "f"(v.w)
                 : "memory");

    if (do_count && c == 0) {
        atomicAdd(cnt + dst, 1.0f);
    }
}

// ---------------------------------------------------------------------------
// Node update: out[n] = act( (aggr[n]/max(cnt,1)) @ Wl^T + bl + x[n] @ Wr^T )
// Weights staged transposed in SMEM (sW[k*OUT+t] = W[t*IN+k]) so the per-k
// read across threads t is bank-conflict-free; feature rows staged in SMEM
// and read via warp broadcast. 256 threads = (256/OUT) nodes per iteration,
// grid-stride so weights load once per block.
// ---------------------------------------------------------------------------
template <int OUT, bool RELU>
__global__ void node_update_kernel(const float* __restrict__ x,
                                   const float* __restrict__ aggr,
                                   const float* __restrict__ cnt,
                                   const float* __restrict__ Wl,
                                   const float* __restrict__ bl,
                                   const float* __restrict__ Wr,
                                   float* __restrict__ out)
{
    constexpr int IN  = 64;
    constexpr int NPB = 256 / OUT;   // nodes per block-iteration

    __shared__ float sWl[IN * OUT];
    __shared__ float sWr[IN * OUT];
    __shared__ float sb[OUT];
    __shared__ float sx[NPB][IN];
    __shared__ float sa[NPB][IN];

    const int tid = threadIdx.x;

    // Stage weights transposed
    for (int i = tid; i < IN * OUT; i += 256) {
        int t = i % OUT;
        int k = i / OUT;
        sWl[i] = Wl[t * IN + k];
        sWr[i] = Wr[t * IN + k];
    }
    if (tid < OUT) sb[tid] = bl[tid];

    const int node_in_blk = tid / OUT;
    const int t           = tid % OUT;

    for (int base = blockIdx.x * NPB; base < N_NODES; base += gridDim.x * NPB) {
        __syncthreads();  // weights ready (1st iter) / sx,sa reuse safe
        // Stage feature + normalized-aggregate rows
        for (int i = tid; i < NPB * IN; i += 256) {
            int nl = i / IN;
            int k  = i % IN;
            int n  = base + nl;
            if (n < N_NODES) {
                float inv = 1.0f / fmaxf(cnt[n], 1.0f);
                sx[nl][k] = x[(size_t)n * IN + k];
                sa[nl][k] = aggr[(size_t)n * IN + k] * inv;
            }
        }
        __syncthreads();

        int n = base + node_in_blk;
        if (n < N_NODES) {
            float acc = sb[t];
#pragma unroll
            for (int k = 0; k < IN; k++) {
                acc += sa[node_in_blk][k] * sWl[k * OUT + t]
                     + sx[node_in_blk][k] * sWr[k * OUT + t];
            }
            if (RELU) acc = fmaxf(acc, 0.0f);
            out[(size_t)n * OUT + t] = acc;
        }
    }
}

// ---------------------------------------------------------------------------
// Launch
// ---------------------------------------------------------------------------
extern "C" void kernel_launch(void* const* d_in, const int* in_sizes, int n_in,
                              void* d_out, int out_size)
{
    const float* x   = (const float*)d_in[0];
    const int*   ei  = (const int*)d_in[1];
    const float* Wl1 = (const float*)d_in[2];
    const float* bl1 = (const float*)d_in[3];
    const float* Wr1 = (const float*)d_in[4];
    const float* Wl2 = (const float*)d_in[5];
    const float* bl2 = (const float*)d_in[6];
    const float* Wr2 = (const float*)d_in[7];
    float*       out = (float*)d_out;

    float *aggr1, *h, *aggr2, *cnt;
    cudaGetSymbolAddress((void**)&aggr1, g_aggr1);
    cudaGetSymbolAddress((void**)&h,     g_h);
    cudaGetSymbolAddress((void**)&aggr2, g_aggr2);
    cudaGetSymbolAddress((void**)&cnt,   g_cnt);

    // Zero accumulators (memset nodes in the captured graph)
    cudaMemsetAsync(aggr1, 0, sizeof(float) * N_NODES * IN_DIM,  0);
    cudaMemsetAsync(aggr2, 0, sizeof(float) * N_NODES * HID_DIM, 0);
    cudaMemsetAsync(cnt,   0, sizeof(float) * N_NODES,           0);

    const int edge_threads = N_EDGES * 16;
    const int edge_blocks  = (edge_threads + 255) / 256;

    // Layer 1
    edge_aggregate_kernel<<<edge_blocks, 256>>>(x, ei, aggr1, cnt, 1);
    node_update_kernel<HID_DIM, true><<<592, 256>>>(x, aggr1, cnt,
                                                    Wl1, bl1, Wr1, h);
    // Layer 2
    edge_aggregate_kernel<<<edge_blocks, 256>>>(h, ei, aggr2, cnt, 0);
    node_update_kernel<OUT_DIM, false><<<592, 256>>>(h, aggr2, cnt,
                                                     Wl2, bl2, Wr2, out);
}